// round 14
// baseline (speedup 1.0000x reference)
#include <cuda_runtime.h>
#include <math.h>
#include <stdint.h>

#define THREADS 512
#define NWARP 16
#define M 8192            // packed complex FFT size
#define NFULL 16384       // real signal length
#define ROWS 512
#define PI_D 3.14159265358979323846

// e^{-i pi/8192} (for W_16384 odd-index fixup)
#define K16C 0.99999992646571785f
#define K16S 0.00038349518757139556f

// ---------------- per-row outputs + completion counter (no allocation) --------
struct RowOut { double pear, cosv, absd, tp, nmi; };
__device__ RowOut  g_row[ROWS];
__device__ unsigned g_done = 0;    // monotonic across launches; (prev % ROWS) picks finalizer

// ---------------- packed f32x2 helpers (sm_103a: only reachable via PTX) ------
__device__ __forceinline__ unsigned long long pk(float2 a){
    unsigned long long u;
    asm("mov.b64 %0, {%1,%2};" : "=l"(u) : "f"(a.x), "f"(a.y));
    return u;
}
__device__ __forceinline__ float2 upk(unsigned long long u){
    float2 r;
    asm("mov.b64 {%0,%1}, %2;" : "=f"(r.x), "=f"(r.y) : "l"(u));
    return r;
}
__device__ __forceinline__ float2 cadd(float2 a, float2 b){
    unsigned long long r, ua = pk(a), ub = pk(b);
    asm("add.rn.f32x2 %0, %1, %2;" : "=l"(r) : "l"(ua), "l"(ub));
    return upk(r);
}
__device__ __forceinline__ float2 csub(float2 a, float2 b){
    unsigned long long r, ua = pk(a), ub = pk(b);
    asm("sub.rn.f32x2 %0, %1, %2;" : "=l"(r) : "l"(ua), "l"(ub));
    return upk(r);
}
// lanewise a*m + c
__device__ __forceinline__ float2 cfma2(float2 a, unsigned long long m, float2 c){
    unsigned long long r, ua = pk(a), uc = pk(c);
    asm("fma.rn.f32x2 %0, %1, %2, %3;" : "=l"(r) : "l"(ua), "l"(m), "l"(uc));
    return upk(r);
}

// ---------------- complex helpers ----------------
__device__ __forceinline__ float2 cmul(float2 a, float2 b){
    return make_float2(a.x*b.x - a.y*b.y, a.x*b.y + a.y*b.x);
}
__device__ __forceinline__ float2 cconj(float2 a){ return make_float2(a.x, -a.y); }

__device__ __forceinline__ float warp_sum(float v){
    #pragma unroll
    for (int o = 16; o; o >>= 1) v += __shfl_down_sync(0xffffffffu, v, o);
    return v;
}
__device__ __forceinline__ double warp_sum_d(double v){
    #pragma unroll
    for (int o = 16; o; o >>= 1) v += __shfl_down_sync(0xffffffffu, v, o);
    return v;
}

// ---------------- table twiddle fetch ----------------
// W_8192^k = e^{-2 pi i k / 8192}, k in [0, 8192); table holds k < 2048
template<int INV>
__device__ __forceinline__ float2 twget(const float2* __restrict__ Wt, int k){
    float2 w = Wt[k & 2047];
    int q = (k >> 11) & 3;
    float2 r = w;
    if (q == 1) r = make_float2( w.y, -w.x);
    else if (q == 2) r = make_float2(-w.x, -w.y);
    else if (q == 3) r = make_float2(-w.y,  w.x);
    if (INV) r.y = -r.y;
    return r;
}
// W_16384^k = e^{-i pi k / 8192}, k in [0, 8192]
template<int INV>
__device__ __forceinline__ float2 twget16k(const float2* __restrict__ Wt, int k){
    float2 w = twget<0>(Wt, k >> 1);
    if (k & 1) w = cmul(w, make_float2(K16C, -K16S));
    if (INV) w.y = -w.y;
    return w;
}

template<int INV>
__device__ __forceinline__ float2 cmulK(float2 a, float wr, float wi){
    float i2 = INV ? -wi : wi;
    return make_float2(a.x*wr - a.y*i2, a.x*i2 + a.y*wr);
}

// radix-4 DIT butterfly (natural-order DFT4), packed-add form.
template<int INV>
__device__ __forceinline__ void bfly4(float2 b0, float2 b1, float2 b2, float2 b3,
                                      float2& o0, float2& o1, float2& o2, float2& o3){
    const unsigned long long CPM = pk(make_float2( 1.f, -1.f));
    const unsigned long long CMP = pk(make_float2(-1.f,  1.f));
    float2 s  = cadd(b0, b2), d  = csub(b0, b2);
    float2 s2 = cadd(b1, b3), d2 = csub(b1, b3);
    o0 = cadd(s, s2); o2 = csub(s, s2);
    float2 d2s = make_float2(d2.y, d2.x);
    if (!INV){ o1 = cfma2(d2s, CPM, d); o3 = cfma2(d2s, CMP, d); }
    else     { o1 = cfma2(d2s, CMP, d); o3 = cfma2(d2s, CPM, d); }
}

// 16-point FFT in registers, natural in/out (two radix-4 micro-passes)
template<int INV>
__device__ __forceinline__ void fft16(float2* x){
    float2 t[16];
    #pragma unroll
    for (int g = 0; g < 4; g++)
        bfly4<INV>(x[g], x[g+4], x[g+8], x[g+12], t[4*g], t[4*g+1], t[4*g+2], t[4*g+3]);
    const float C1 = 0.9238795325112867f, S1 = 0.3826834323650898f, R2 = 0.7071067811865476f;
    bfly4<INV>(t[0], t[4], t[8], t[12], x[0], x[4], x[8], x[12]);
    bfly4<INV>(t[1], cmulK<INV>(t[5],  C1, -S1), cmulK<INV>(t[9],  R2, -R2), cmulK<INV>(t[13],  S1, -C1),
               x[1], x[5], x[9], x[13]);
    bfly4<INV>(t[2], cmulK<INV>(t[6],  R2, -R2), cmulK<INV>(t[10], 0.f, -1.f), cmulK<INV>(t[14], -R2, -R2),
               x[2], x[6], x[10], x[14]);
    bfly4<INV>(t[3], cmulK<INV>(t[7],  S1, -C1), cmulK<INV>(t[11], -R2, -R2), cmulK<INV>(t[15], -C1,  S1),
               x[3], x[7], x[11], x[15]);
}

// ---------------- element swizzle (AoS float2 planes) ----------------
__device__ __forceinline__ int swz1(int a){ return a ^ ((a >> 4) & 31); }

// Stockham radix-16 pass, L=1 (twiddle-free), natural reads, swz1 writes
template<int INV>
__device__ __forceinline__ void pass16p(const float2* __restrict__ zi, float2* __restrict__ zo){
    int j = threadIdx.x;
    float2 x[16];
    #pragma unroll
    for (int c = 0; c < 16; c++) x[c] = zi[j + 512*c];
    fft16<INV>(x);
    #pragma unroll
    for (int c = 0; c < 16; c++) zo[swz1(16*j + c)] = x[c];
}

// Stockham radix-16 pass at sub-length L = 2^LOG2L (L in {16, 256}), w1 from tiny table.
template<int LOG2L, int INV, int SWR>
__device__ __forceinline__ void passR16(const float2* __restrict__ zi, float2* __restrict__ zo,
                                        const float2* __restrict__ wtab){
    const int L = 1 << LOG2L;
    int j = threadIdx.x;
    int r = j & (L - 1);
    int s = j >> LOG2L;
    float2 x[16];
    #pragma unroll
    for (int m = 0; m < 16; m++){
        int a = j + 512*m;
        if (SWR) a = swz1(a);
        x[m] = zi[a];
    }
    float2 w1 = wtab[r];
    if (INV) w1.y = -w1.y;
    float2 w2 = cmul(w1, w1);
    float2 w3 = cmul(w2, w1);
    float2 w4 = cmul(w2, w2);
    float2 w8 = cmul(w4, w4);
    x[1]  = cmul(x[1],  w1);
    x[2]  = cmul(x[2],  w2);
    x[3]  = cmul(x[3],  w3);
    x[4]  = cmul(x[4],  w4);
    x[5]  = cmul(x[5],  cmul(w4, w1));
    x[6]  = cmul(x[6],  cmul(w4, w2));
    x[7]  = cmul(x[7],  cmul(w4, w3));
    x[8]  = cmul(x[8],  w8);
    x[9]  = cmul(x[9],  cmul(w8, w1));
    x[10] = cmul(x[10], cmul(w8, w2));
    x[11] = cmul(x[11], cmul(w8, w3));
    x[12] = cmul(x[12], cmul(w8, w4));
    x[13] = cmul(x[13], cmul(w8, cmul(w4, w1)));
    x[14] = cmul(x[14], cmul(w8, cmul(w4, w2)));
    x[15] = cmul(x[15], cmul(w8, cmul(w4, w3)));
    fft16<INV>(x);
    int base = r + (s << (LOG2L + 4));
    #pragma unroll
    for (int c = 0; c < 16; c++)
        zo[base + (c << LOG2L)] = x[c];
}

// final Stockham radix-2 pass (L=4096), forward chains only
template<int INV>
__device__ __forceinline__ void pass2(const float2* __restrict__ zi, float2* __restrict__ zo,
                                      const float2* __restrict__ Wt){
    #pragma unroll
    for (int it = 0; it < 8; it++){
        int j = threadIdx.x + it * 512;
        float2 a = zi[j];
        float2 v = cmul(zi[j + 4096], twget<INV>(Wt, j));
        zo[j]        = cadd(a, v);
        zo[j + 4096] = csub(a, v);
    }
}

// returns 2*X[k] of the length-16384 real signal (uniform exact scale; all
// consumers — power-spectrum ratio, normalized phase corr, argmax — invariant)
__device__ __forceinline__ float2 spec_at(const float2* __restrict__ Z, int k, float2 w){
    float2 a = Z[k & (M - 1)];
    float2 b = Z[(M - k) & (M - 1)];
    float2 E = make_float2(a.x + b.x, a.y - b.y);
    float2 O = make_float2(a.y + b.y, b.x - a.x);
    return cadd(E, cmul(w, O));
}

// warp-aggregated histogram add (Gaussian data -> heavy same-bucket collisions;
// aggregation removes intra-warp same-address ATOMS serialization)
__device__ __forceinline__ void hadd(unsigned* hist, int b){
    unsigned m = __match_any_sync(0xffffffffu, b);
    int leader = __ffs(m) - 1;
    if ((int)(threadIdx.x & 31) == leader) atomicAdd(&hist[b], __popc(m));
}

// ---------------- single fused kernel: one CTA per row, last CTA finalizes ----
__global__ __launch_bounds__(THREADS, 1)
void row_kernel(const float* __restrict__ pred, const float* __restrict__ targ,
                const int* __restrict__ pi, const int* __restrict__ pep,
                float* __restrict__ out){
    extern __shared__ float2 smz[];
    float2* Ap = smz;               // 8192
    float2* Bp = smz + 8192;        // 8192
    float2* Cp = smz + 16384;       // 8192
    float2* Wt  = smz + 24576;      // 2048: W_8192^k, k<2048
    float2* w4t = smz + 26624;      // 16:   e^{-i pi r/128}
    float2* w8t = smz + 26640;      // 256:  e^{-i pi r/2048}

    __shared__ float    s_red[NWARP][10];
    __shared__ int      s_idx[NWARP];
    __shared__ float    s_mm[4];
    __shared__ unsigned hist[100];
    __shared__ float    s_hx[10], s_hy[10];
    __shared__ float2   s_c8192;
    __shared__ unsigned s_last;
    __shared__ double   s_fin[NWARP][5];

    const int tid  = threadIdx.x;
    const int warp = tid >> 5, lane = tid & 31;
    const int row  = blockIdx.x;
    const int i0   = *pi;

    double r_pear = 0.0, r_cos = 0.0, r_absd = 0.0, r_tp = 0.0, r_nmi = 0.0;

    const float4* xr4 = (const float4*)(pred + ((size_t)i0 * ROWS + row) * (size_t)NFULL);
    const float4* yr4 = (const float4*)(targ + (size_t)row * (size_t)NFULL);

    if (tid < 100) hist[tid] = 0u;

    // ---- one-time twiddle tables (accurate sincospif; ~5 calls/thread) ----
    #pragma unroll
    for (int it = 0; it < 4; it++){
        int t = tid + it * 512;
        float s, c; sincospif(-(float)t * (1.0f/4096.0f), &s, &c);
        Wt[t] = make_float2(c, s);
    }
    if (tid < 16){ float s, c; sincospif(-(float)tid * (1.0f/128.0f),  &s, &c); w4t[tid] = make_float2(c, s); }
    if (tid < 256){ float s, c; sincospif(-(float)tid * (1.0f/2048.0f), &s, &c); w8t[tid] = make_float2(c, s); }

    // ---- load (float4 = 2 complex) + Pearson moments + min/max ----
    float sx = 0.f, sy = 0.f, sxy = 0.f, sx2 = 0.f, sy2 = 0.f;
    float xmn = INFINITY, xmx = -INFINITY, ymn = INFINITY, ymx = -INFINITY;
    #pragma unroll 4
    for (int it = 0; it < 8; it++){
        int n = tid + it * THREADS;       // 0..4095 float4s
        float4 a = xr4[n], b = yr4[n];
        sx  += (a.x + a.y) + (a.z + a.w);
        sy  += (b.x + b.y) + (b.z + b.w);
        sxy += (a.x*b.x + a.y*b.y) + (a.z*b.z + a.w*b.w);
        sx2 += (a.x*a.x + a.y*a.y) + (a.z*a.z + a.w*a.w);
        sy2 += (b.x*b.x + b.y*b.y) + (b.z*b.z + b.w*b.w);
        xmn = fminf(xmn, fminf(fminf(a.x, a.y), fminf(a.z, a.w)));
        xmx = fmaxf(xmx, fmaxf(fmaxf(a.x, a.y), fmaxf(a.z, a.w)));
        ymn = fminf(ymn, fminf(fminf(b.x, b.y), fminf(b.z, b.w)));
        ymx = fmaxf(ymx, fmaxf(fmaxf(b.x, b.y), fmaxf(b.z, b.w)));
        ((float4*)Ap)[n] = a;
        ((float4*)Bp)[n] = b;
    }
    sx  = warp_sum(sx);  sy  = warp_sum(sy); sxy = warp_sum(sxy);
    sx2 = warp_sum(sx2); sy2 = warp_sum(sy2);
    #pragma unroll
    for (int o = 16; o; o >>= 1){
        xmn = fminf(xmn, __shfl_down_sync(0xffffffffu, xmn, o));
        xmx = fmaxf(xmx, __shfl_down_sync(0xffffffffu, xmx, o));
        ymn = fminf(ymn, __shfl_down_sync(0xffffffffu, ymn, o));
        ymx = fmaxf(ymx, __shfl_down_sync(0xffffffffu, ymx, o));
    }
    if (lane == 0){
        s_red[warp][0]=sx;  s_red[warp][1]=sy;  s_red[warp][2]=sxy;
        s_red[warp][3]=sx2; s_red[warp][4]=sy2;
        s_red[warp][5]=xmn; s_red[warp][6]=xmx; s_red[warp][7]=ymn; s_red[warp][8]=ymx;
    }
    __syncthreads();
    if (tid == 0){
        double Sx=0,Sy=0,Sxy=0,Sx2=0,Sy2=0;
        float a = s_red[0][5], b = s_red[0][6], c = s_red[0][7], d = s_red[0][8];
        for (int w = 0; w < NWARP; w++){
            Sx+=s_red[w][0]; Sy+=s_red[w][1]; Sxy+=s_red[w][2];
            Sx2+=s_red[w][3]; Sy2+=s_red[w][4];
            a = fminf(a, s_red[w][5]); b = fmaxf(b, s_red[w][6]);
            c = fminf(c, s_red[w][7]); d = fmaxf(d, s_red[w][8]);
        }
        const double N = (double)NFULL;
        r_pear = 1.0 - (N*Sxy - Sx*Sy) / sqrt((N*Sx2 - Sx*Sx) * (N*Sy2 - Sy*Sy));
        s_mm[0]=a; s_mm[1]=b; s_mm[2]=c; s_mm[3]=d;
    }
    __syncthreads();

    // ---- pred FFT pass 1 (A -> C, L=1) with MI histogram fused (warp-aggregated) ----
    {
        const float xmin = s_mm[0], ymin = s_mm[2];
        const float bwx = __fdiv_rn(s_mm[1] - s_mm[0], 10.0f);
        const float bwy = __fdiv_rn(s_mm[3] - s_mm[2], 10.0f);
        int j = tid;
        float2 x[16];
        #pragma unroll
        for (int c = 0; c < 16; c++){
            int n = j + 512*c;
            float2 a = Ap[n];
            float2 b = Bp[n];
            x[c] = a;
            int ix0 = min(max((int)__fdiv_rn(a.x - xmin, bwx), 0), 9);
            int iy0 = min(max((int)__fdiv_rn(b.x - ymin, bwy), 0), 9);
            int ix1 = min(max((int)__fdiv_rn(a.y - xmin, bwx), 0), 9);
            int iy1 = min(max((int)__fdiv_rn(b.y - ymin, bwy), 0), 9);
            hadd(hist, ix0 * 10 + iy0);
            hadd(hist, ix1 * 10 + iy1);
        }
        fft16<0>(x);
        #pragma unroll
        for (int c = 0; c < 16; c++) Cp[swz1(16*j + c)] = x[c];
    }
    __syncthreads();

    // ---- MI final math on warp 0 (hist stable; other warps proceed) ----
    if (warp == 0){
        const float eps = 1e-8f;
        const float invD = 1.0f / 8388608.0f;   // 1/(B*S), faithful to reference
        if (lane < 10){
            float hx = 0.f, hy = 0.f;
            for (int j = 0; j < 10; j++){
                hx += (float)hist[lane*10 + j];
                hy += (float)hist[j*10 + lane];
            }
            s_hx[lane] = hx; s_hy[lane] = hy;
        }
        __syncwarp();
        float mi = 0.f;
        for (int b = lane; b < 100; b += 32){
            float px  = s_hx[b/10] * invD;
            float py  = s_hy[b%10] * invD;
            float pxy = (float)hist[b] * invD;
            mi += pxy * logf(__fdiv_rn(pxy + eps, px * py + eps));
        }
        mi = warp_sum(mi);
        float he = 0.f;
        if (lane < 10){
            float px = s_hx[lane] * invD, py = s_hy[lane] * invD;
            he = -px * logf(px + eps) - py * logf(py + eps);
        }
        he = warp_sum(he);
        if (lane == 0) r_nmi = (double)(mi / (0.5f * he));
    }

    passR16<4,0,1>(Cp, Ap, w4t); __syncthreads();
    passR16<8,0,0>(Ap, Cp, w8t); __syncthreads();
    pass2<0>(Cp, Ap, Wt);        __syncthreads();   // pred spectrum in A

    // ---- targ forward FFT: B <-> C ----
    pass16p<0>(Bp, Cp);          __syncthreads();
    passR16<4,0,1>(Cp, Bp, w4t); __syncthreads();
    passR16<8,0,0>(Bp, Cp, w8t); __syncthreads();
    pass2<0>(Cp, Bp, Wt);        __syncthreads();   // targ spectrum in B

    // ---- spectra: power-spectrum sums + hann-windowed phase correlation -> C ----
    float accd = 0.f, acct = 0.f;
    float2 lastX0p, lastX0t, lastXpp, lastXpt;
    for (int it = 0; it < 16; it++){
        int k = tid + it * 512;               // 0..8191
        float2 w0 = twget16k<0>(Wt, k);
        float2 X0p = spec_at(Ap, k, w0);
        float2 X0t = spec_at(Bp, k, w0);
        float2 Xmp, Xmt, Xpp, Xpt;
        Xmp.x = __shfl_up_sync(0xffffffffu, X0p.x, 1);
        Xmp.y = __shfl_up_sync(0xffffffffu, X0p.y, 1);
        Xmt.x = __shfl_up_sync(0xffffffffu, X0t.x, 1);
        Xmt.y = __shfl_up_sync(0xffffffffu, X0t.y, 1);
        Xpp.x = __shfl_down_sync(0xffffffffu, X0p.x, 1);
        Xpp.y = __shfl_down_sync(0xffffffffu, X0p.y, 1);
        Xpt.x = __shfl_down_sync(0xffffffffu, X0t.x, 1);
        Xpt.y = __shfl_down_sync(0xffffffffu, X0t.y, 1);
        if (lane == 0){
            if (k == 0){
                float2 w1 = twget16k<0>(Wt, 1);
                Xmp = cconj(spec_at(Ap, 1, w1));   // X[-1] = conj(X[1])
                Xmt = cconj(spec_at(Bp, 1, w1));
            } else {
                float2 wm = twget16k<0>(Wt, k-1);
                Xmp = spec_at(Ap, k-1, wm);
                Xmt = spec_at(Bp, k-1, wm);
            }
        }
        if (lane == 31){
            float2 wp = twget16k<0>(Wt, k+1);
            Xpp = spec_at(Ap, k+1, wp);
            Xpt = spec_at(Bp, k+1, wp);
        }
        float pp = X0p.x*X0p.x + X0p.y*X0p.y;
        float pt = X0t.x*X0t.x + X0t.y*X0t.y;
        accd += fabsf(pp - pt);
        acct += pt;
        float2 xf = csub(cadd(X0p, X0p), cadd(Xmp, Xpp));
        float2 tf = csub(cadd(X0t, X0t), cadd(Xmt, Xpt));
        float2 c = cmul(xf, cconj(tf));
        float inv = rsqrtf(c.x*c.x + c.y*c.y);
        Cp[k] = make_float2(c.x * inv, c.y * inv);
        lastX0p = X0p; lastX0t = X0t; lastXpp = Xpp; lastXpt = Xpt;
    }
    if (tid == THREADS - 1){
        // bin 8192: X0' = X[8192] (= lastXpp), Xm' = X[8191], Xp' = conj(X[8191])
        float2 X0p = lastXpp, X0t = lastXpt;
        float2 Xmp = lastX0p, Xmt = lastX0t;
        float2 Xpp = cconj(Xmp), Xpt = cconj(Xmt);
        float pp = X0p.x*X0p.x + X0p.y*X0p.y;
        float pt = X0t.x*X0t.x + X0t.y*X0t.y;
        accd += fabsf(pp - pt);
        acct += pt;
        float2 xf = csub(cadd(X0p, X0p), cadd(Xmp, Xpp));
        float2 tf = csub(cadd(X0t, X0t), cadd(Xmt, Xpt));
        float2 c = cmul(xf, cconj(tf));
        float inv = rsqrtf(c.x*c.x + c.y*c.y);
        s_c8192 = make_float2(c.x * inv, c.y * inv);
    }
    accd = warp_sum(accd); acct = warp_sum(acct);
    if (lane == 0){ s_red[warp][0] = accd; s_red[warp][1] = acct; }
    __syncthreads();
    if (tid == 0){
        double d = 0.0, t2 = 0.0;
        for (int w = 0; w < NWARP; w++){ d += s_red[w][0]; t2 += s_red[w][1]; }
        r_absd = d; r_tp = t2;
    }

    // ---- inverse pass 1 with spectrum-pack folded in: C -> A (swz1 writes) ----
    {
        int j = tid;
        float2 x[16];
        #pragma unroll
        for (int c = 0; c < 16; c++){
            int n = j + 512*c;
            float2 Bn = Cp[n];
            float2 Bm = (n == 0) ? s_c8192 : cconj(Cp[8192 - n]);  // conj(C[8192-n])
            float2 E = cadd(Bn, Bm);
            float2 D = csub(Bn, Bm);
            float2 wn = twget16k<1>(Wt, n);          // e^{+i pi n/8192}
            float2 O  = cmul(wn, D);
            x[c] = make_float2(E.x - O.y, E.y + O.x);  // E + i*O
        }
        fft16<1>(x);
        #pragma unroll
        for (int c = 0; c < 16; c++) Ap[swz1(16*j + c)] = x[c];
    }
    __syncthreads();

    passR16<4,1,1>(Ap, Cp, w4t); __syncthreads();
    passR16<8,1,0>(Cp, Ap, w8t); __syncthreads();   // inverse penultimate in A

    // ---- argmax with final radix-2 pass folded in (first-occurrence tie break) ----
    float best = -INFINITY; int bi = 0x7fffffff;
    #pragma unroll 2
    for (int it = 0; it < 8; it++){
        int jj = tid + it * 512;              // 0..4095
        float2 u = Ap[jj];
        float2 v = Ap[jj + 4096];
        float2 wv = cmul(v, twget<1>(Wt, jj));
        float y0r = u.x + wv.x, y0i = u.y + wv.y;   // Z[jj]      -> times 2jj, 2jj+1
        float y1r = u.x - wv.x, y1i = u.y - wv.y;   // Z[jj+4096] -> times 2jj+8192, +8193
        int e0 = 2*jj, o0 = 2*jj + 1, e1 = 2*jj + 8192, o1 = 2*jj + 8193;
        if (y0r > best || (y0r == best && e0 < bi)){ best = y0r; bi = e0; }
        if (y0i > best || (y0i == best && o0 < bi)){ best = y0i; bi = o0; }
        if (y1r > best || (y1r == best && e1 < bi)){ best = y1r; bi = e1; }
        if (y1i > best || (y1i == best && o1 < bi)){ best = y1i; bi = o1; }
    }
    #pragma unroll
    for (int off = 16; off; off >>= 1){
        float ov = __shfl_down_sync(0xffffffffu, best, off);
        int   oi = __shfl_down_sync(0xffffffffu, bi,   off);
        if (ov > best || (ov == best && oi < bi)){ best = ov; bi = oi; }
    }
    if (lane == 0){ s_red[warp][0] = best; s_idx[warp] = bi; }
    __syncthreads();
    if (tid == 0){
        best = s_red[0][0]; bi = s_idx[0];
        for (int w = 1; w < NWARP; w++){
            float v = s_red[w][0]; int ix = s_idx[w];
            if (v > best || (v == best && ix < bi)){ best = v; bi = ix; }
        }
        r_cos = (double)cosf(2.0f * (float)PI_D * (float)bi / 16384.0f);

        // publish this row's results (release), then arrive
        g_row[row].pear = r_pear;
        g_row[row].cosv = r_cos;
        g_row[row].absd = r_absd;
        g_row[row].tp   = r_tp;
        g_row[row].nmi  = r_nmi;
        __threadfence();
        unsigned prev = atomicAdd(&g_done, 1u);
        s_last = ((prev % ROWS) == ROWS - 1) ? 1u : 0u;
        if (s_last) __threadfence();   // acquire: order g_row reads after counter observation
    }
    __syncthreads();

    // ---- last CTA reduces all rows and writes the scalar loss ----
    if (s_last){
        double pe = 0.0, co = 0.0, ad = 0.0, tp = 0.0, nm = 0.0;
        for (int r = tid; r < ROWS; r += THREADS){
            const double* p = (const double*)&g_row[r];
            pe += __ldcg(p + 0);
            co += __ldcg(p + 1);
            ad += __ldcg(p + 2);
            tp += __ldcg(p + 3);
            nm += __ldcg(p + 4);
        }
        pe = warp_sum_d(pe); co = warp_sum_d(co); ad = warp_sum_d(ad);
        tp = warp_sum_d(tp); nm = warp_sum_d(nm);
        if (lane == 0){
            s_fin[warp][0]=pe; s_fin[warp][1]=co; s_fin[warp][2]=ad;
            s_fin[warp][3]=tp; s_fin[warp][4]=nm;
        }
        __syncthreads();
        if (tid == 0){
            double Pe=0, Co=0, Ad=0, Tp=0, Nm=0;
            for (int w = 0; w < NWARP; w++){
                Pe+=s_fin[w][0]; Co+=s_fin[w][1]; Ad+=s_fin[w][2];
                Tp+=s_fin[w][3]; Nm+=s_fin[w][4];
            }
            int ep = *pep;
            double loss = Pe / (double)ROWS;
            if (ep >= 400){
                loss += 1.0 - Co / (double)ROWS;   // phase correlation
                loss += Ad / Tp;                   // power spectrum
            }
            if (ep >= 700){
                loss += 1.0 - Nm / (double)ROWS;   // mutual information
            }
            out[0] = (float)loss;
        }
    }
}

// ---------------- launch ----------------
extern "C" void kernel_launch(void* const* d_in, const int* in_sizes, int n_in,
                              void* d_out, int out_size){
    const float* pred = (const float*)d_in[0];
    const float* targ = (const float*)d_in[1];
    const int*   pi   = (const int*)d_in[2];
    const int*   pep  = (const int*)d_in[3];
    float* out = (float*)d_out;

    // 3 planes of 8192 float2 + (2048+16+256) float2 twiddles = 215168 bytes
    const size_t smem_bytes = (size_t)(24576 + 2048 + 16 + 256) * sizeof(float2);
    cudaFuncSetAttribute(row_kernel, cudaFuncAttributeMaxDynamicSharedMemorySize,
                         (int)smem_bytes);

    row_kernel<<<ROWS, THREADS, smem_bytes>>>(pred, targ, pi, pep, out);
}

// round 15
// speedup vs baseline: 1.9104x; 1.9104x over previous
#include <cuda_runtime.h>
#include <math.h>
#include <stdint.h>

#define THREADS 512
#define NWARP 16
#define M 8192            // packed complex FFT size
#define NFULL 16384       // real signal length
#define ROWS 512
#define PI_D 3.14159265358979323846

// e^{-i pi/8192} (for W_16384 odd-index fixup)
#define K16C 0.99999992646571785f
#define K16S 0.00038349518757139556f

// ---------------- per-row outputs + completion counter (no allocation) --------
struct RowOut { double pear, cosv, absd, tp, nmi; };
__device__ RowOut  g_row[ROWS];
__device__ unsigned g_done = 0;    // monotonic across launches; (prev % ROWS) picks finalizer

// ---------------- packed f32x2 helpers (sm_103a: only reachable via PTX) ------
__device__ __forceinline__ unsigned long long pk(float2 a){
    unsigned long long u;
    asm("mov.b64 %0, {%1,%2};" : "=l"(u) : "f"(a.x), "f"(a.y));
    return u;
}
__device__ __forceinline__ float2 upk(unsigned long long u){
    float2 r;
    asm("mov.b64 {%0,%1}, %2;" : "=f"(r.x), "=f"(r.y) : "l"(u));
    return r;
}
__device__ __forceinline__ float2 cadd(float2 a, float2 b){
    unsigned long long r, ua = pk(a), ub = pk(b);
    asm("add.rn.f32x2 %0, %1, %2;" : "=l"(r) : "l"(ua), "l"(ub));
    return upk(r);
}
__device__ __forceinline__ float2 csub(float2 a, float2 b){
    unsigned long long r, ua = pk(a), ub = pk(b);
    asm("sub.rn.f32x2 %0, %1, %2;" : "=l"(r) : "l"(ua), "l"(ub));
    return upk(r);
}
// lanewise a*m + c
__device__ __forceinline__ float2 cfma2(float2 a, unsigned long long m, float2 c){
    unsigned long long r, ua = pk(a), uc = pk(c);
    asm("fma.rn.f32x2 %0, %1, %2, %3;" : "=l"(r) : "l"(ua), "l"(m), "l"(uc));
    return upk(r);
}

// ---------------- complex helpers ----------------
__device__ __forceinline__ float2 cmul(float2 a, float2 b){
    return make_float2(a.x*b.x - a.y*b.y, a.x*b.y + a.y*b.x);
}
__device__ __forceinline__ float2 cconj(float2 a){ return make_float2(a.x, -a.y); }

__device__ __forceinline__ float warp_sum(float v){
    #pragma unroll
    for (int o = 16; o; o >>= 1) v += __shfl_down_sync(0xffffffffu, v, o);
    return v;
}
__device__ __forceinline__ double warp_sum_d(double v){
    #pragma unroll
    for (int o = 16; o; o >>= 1) v += __shfl_down_sync(0xffffffffu, v, o);
    return v;
}

// ---------------- table twiddle fetch ----------------
template<int INV>
__device__ __forceinline__ float2 twget(const float2* __restrict__ Wt, int k){
    float2 w = Wt[k & 2047];
    int q = (k >> 11) & 3;
    float2 r = w;
    if (q == 1) r = make_float2( w.y, -w.x);
    else if (q == 2) r = make_float2(-w.x, -w.y);
    else if (q == 3) r = make_float2(-w.y,  w.x);
    if (INV) r.y = -r.y;
    return r;
}
template<int INV>
__device__ __forceinline__ float2 twget16k(const float2* __restrict__ Wt, int k){
    float2 w = twget<0>(Wt, k >> 1);
    if (k & 1) w = cmul(w, make_float2(K16C, -K16S));
    if (INV) w.y = -w.y;
    return w;
}

template<int INV>
__device__ __forceinline__ float2 cmulK(float2 a, float wr, float wi){
    float i2 = INV ? -wi : wi;
    return make_float2(a.x*wr - a.y*i2, a.x*i2 + a.y*wr);
}

// radix-4 DIT butterfly (natural-order DFT4), packed-add form.
template<int INV>
__device__ __forceinline__ void bfly4(float2 b0, float2 b1, float2 b2, float2 b3,
                                      float2& o0, float2& o1, float2& o2, float2& o3){
    const unsigned long long CPM = pk(make_float2( 1.f, -1.f));
    const unsigned long long CMP = pk(make_float2(-1.f,  1.f));
    float2 s  = cadd(b0, b2), d  = csub(b0, b2);
    float2 s2 = cadd(b1, b3), d2 = csub(b1, b3);
    o0 = cadd(s, s2); o2 = csub(s, s2);
    float2 d2s = make_float2(d2.y, d2.x);
    if (!INV){ o1 = cfma2(d2s, CPM, d); o3 = cfma2(d2s, CMP, d); }
    else     { o1 = cfma2(d2s, CMP, d); o3 = cfma2(d2s, CPM, d); }
}

// 16-point FFT in registers, natural in/out (two radix-4 micro-passes)
template<int INV>
__device__ __forceinline__ void fft16(float2* x){
    float2 t[16];
    #pragma unroll
    for (int g = 0; g < 4; g++)
        bfly4<INV>(x[g], x[g+4], x[g+8], x[g+12], t[4*g], t[4*g+1], t[4*g+2], t[4*g+3]);
    const float C1 = 0.9238795325112867f, S1 = 0.3826834323650898f, R2 = 0.7071067811865476f;
    bfly4<INV>(t[0], t[4], t[8], t[12], x[0], x[4], x[8], x[12]);
    bfly4<INV>(t[1], cmulK<INV>(t[5],  C1, -S1), cmulK<INV>(t[9],  R2, -R2), cmulK<INV>(t[13],  S1, -C1),
               x[1], x[5], x[9], x[13]);
    bfly4<INV>(t[2], cmulK<INV>(t[6],  R2, -R2), cmulK<INV>(t[10], 0.f, -1.f), cmulK<INV>(t[14], -R2, -R2),
               x[2], x[6], x[10], x[14]);
    bfly4<INV>(t[3], cmulK<INV>(t[7],  S1, -C1), cmulK<INV>(t[11], -R2, -R2), cmulK<INV>(t[15], -C1,  S1),
               x[3], x[7], x[11], x[15]);
}

// ---------------- element swizzle (AoS float2 planes) ----------------
__device__ __forceinline__ int swz1(int a){ return a ^ ((a >> 4) & 31); }

// ---------------- merged (pred+targ) forward passes: in-place, mid-barrier ----
// Reads both planes fully into registers, mid-barrier, writes both planes.
// Twiddle powers computed once, applied to both chains.
template<int LOG2L, int SWR>
__device__ __forceinline__ void mpassR16(float2* Pa, float2* Pb, const float2* __restrict__ wtab){
    const int L = 1 << LOG2L;
    int j = threadIdx.x;
    int r = j & (L - 1);
    int s = j >> LOG2L;
    float2 xa[16], xb[16];
    #pragma unroll
    for (int m = 0; m < 16; m++){
        int a = j + 512*m;
        if (SWR) a = swz1(a);
        xa[m] = Pa[a];
        xb[m] = Pb[a];
    }
    {
        float2 w1 = wtab[r];
        float2 w2 = cmul(w1, w1);
        float2 w3 = cmul(w2, w1);
        float2 w4 = cmul(w2, w2);
        float2 w8 = cmul(w4, w4);
        float2 p;
        p = w1;               xa[1]  = cmul(xa[1],  p); xb[1]  = cmul(xb[1],  p);
        p = w2;               xa[2]  = cmul(xa[2],  p); xb[2]  = cmul(xb[2],  p);
        p = w3;               xa[3]  = cmul(xa[3],  p); xb[3]  = cmul(xb[3],  p);
        p = w4;               xa[4]  = cmul(xa[4],  p); xb[4]  = cmul(xb[4],  p);
        p = cmul(w4, w1);     xa[5]  = cmul(xa[5],  p); xb[5]  = cmul(xb[5],  p);
        p = cmul(w4, w2);     xa[6]  = cmul(xa[6],  p); xb[6]  = cmul(xb[6],  p);
        p = cmul(w4, w3);     xa[7]  = cmul(xa[7],  p); xb[7]  = cmul(xb[7],  p);
        p = w8;               xa[8]  = cmul(xa[8],  p); xb[8]  = cmul(xb[8],  p);
        p = cmul(w8, w1);     xa[9]  = cmul(xa[9],  p); xb[9]  = cmul(xb[9],  p);
        p = cmul(w8, w2);     xa[10] = cmul(xa[10], p); xb[10] = cmul(xb[10], p);
        p = cmul(w8, w3);     xa[11] = cmul(xa[11], p); xb[11] = cmul(xb[11], p);
        p = cmul(w8, w4);     xa[12] = cmul(xa[12], p); xb[12] = cmul(xb[12], p);
        p = cmul(w8, cmul(w4, w1)); xa[13] = cmul(xa[13], p); xb[13] = cmul(xb[13], p);
        p = cmul(w8, cmul(w4, w2)); xa[14] = cmul(xa[14], p); xb[14] = cmul(xb[14], p);
        p = cmul(w8, cmul(w4, w3)); xa[15] = cmul(xa[15], p); xb[15] = cmul(xb[15], p);
    }
    fft16<0>(xa);
    fft16<0>(xb);
    __syncthreads();               // all reads complete before in-place writes
    int base = r + (s << (LOG2L + 4));
    #pragma unroll
    for (int c = 0; c < 16; c++){
        int a = base + (c << LOG2L);
        Pa[a] = xa[c]; Pb[a] = xb[c];
    }
}

// merged final radix-2 (L=4096): per-thread read-set == write-set -> in-place,
// no mid-barrier needed; shared twiddle fetch.
__device__ __forceinline__ void mpass2(float2* Pa, float2* Pb, const float2* __restrict__ Wt){
    #pragma unroll
    for (int it = 0; it < 8; it++){
        int j = threadIdx.x + it * 512;
        float2 w = twget<0>(Wt, j);
        float2 a = Pa[j];
        float2 v = cmul(Pa[j + 4096], w);
        Pa[j] = cadd(a, v); Pa[j + 4096] = csub(a, v);
        float2 a2 = Pb[j];
        float2 v2 = cmul(Pb[j + 4096], w);
        Pb[j] = cadd(a2, v2); Pb[j + 4096] = csub(a2, v2);
    }
}

// single-chain Stockham radix-16 (inverse side), ping-pong
template<int LOG2L, int INV, int SWR>
__device__ __forceinline__ void passR16(const float2* __restrict__ zi, float2* __restrict__ zo,
                                        const float2* __restrict__ wtab){
    const int L = 1 << LOG2L;
    int j = threadIdx.x;
    int r = j & (L - 1);
    int s = j >> LOG2L;
    float2 x[16];
    #pragma unroll
    for (int m = 0; m < 16; m++){
        int a = j + 512*m;
        if (SWR) a = swz1(a);
        x[m] = zi[a];
    }
    float2 w1 = wtab[r];
    if (INV) w1.y = -w1.y;
    float2 w2 = cmul(w1, w1);
    float2 w3 = cmul(w2, w1);
    float2 w4 = cmul(w2, w2);
    float2 w8 = cmul(w4, w4);
    x[1]  = cmul(x[1],  w1);
    x[2]  = cmul(x[2],  w2);
    x[3]  = cmul(x[3],  w3);
    x[4]  = cmul(x[4],  w4);
    x[5]  = cmul(x[5],  cmul(w4, w1));
    x[6]  = cmul(x[6],  cmul(w4, w2));
    x[7]  = cmul(x[7],  cmul(w4, w3));
    x[8]  = cmul(x[8],  w8);
    x[9]  = cmul(x[9],  cmul(w8, w1));
    x[10] = cmul(x[10], cmul(w8, w2));
    x[11] = cmul(x[11], cmul(w8, w3));
    x[12] = cmul(x[12], cmul(w8, w4));
    x[13] = cmul(x[13], cmul(w8, cmul(w4, w1)));
    x[14] = cmul(x[14], cmul(w8, cmul(w4, w2)));
    x[15] = cmul(x[15], cmul(w8, cmul(w4, w3)));
    fft16<INV>(x);
    int base = r + (s << (LOG2L + 4));
    #pragma unroll
    for (int c = 0; c < 16; c++)
        zo[base + (c << LOG2L)] = x[c];
}

// returns 2*X[k] of the length-16384 real signal (uniform exact scale)
__device__ __forceinline__ float2 spec_at(const float2* __restrict__ Z, int k, float2 w){
    float2 a = Z[k & (M - 1)];
    float2 b = Z[(M - k) & (M - 1)];
    float2 E = make_float2(a.x + b.x, a.y - b.y);
    float2 O = make_float2(a.y + b.y, b.x - a.x);
    return cadd(E, cmul(w, O));
}

// ---------------- single fused kernel: one CTA per row, last CTA finalizes ----
__global__ __launch_bounds__(THREADS, 1)
void row_kernel(const float* __restrict__ pred, const float* __restrict__ targ,
                const int* __restrict__ pi, const int* __restrict__ pep,
                float* __restrict__ out){
    extern __shared__ float2 smz[];
    float2* Ap = smz;               // 8192  (pred chain, in-place)
    float2* Bp = smz + 8192;        // 8192  (targ chain, in-place)
    float2* Cp = smz + 16384;       // 8192  (phase-corr / inverse scratch)
    float2* Wt  = smz + 24576;      // 2048: W_8192^k, k<2048
    float2* w4t = smz + 26624;      // 16:   e^{-i pi r/128}
    float2* w8t = smz + 26640;      // 256:  e^{-i pi r/2048}

    __shared__ float    s_red[NWARP][10];
    __shared__ int      s_idx[NWARP];
    __shared__ float    s_mm[4];
    __shared__ unsigned hist[100];
    __shared__ float    s_hx[10], s_hy[10];
    __shared__ float2   s_c8192;
    __shared__ unsigned s_last;
    __shared__ double   s_fin[NWARP][5];

    const int tid  = threadIdx.x;
    const int warp = tid >> 5, lane = tid & 31;
    const int row  = blockIdx.x;
    const int i0   = *pi;

    double r_pear = 0.0, r_cos = 0.0, r_absd = 0.0, r_tp = 0.0, r_nmi = 0.0;

    const float2* xr = (const float2*)(pred + ((size_t)i0 * ROWS + row) * (size_t)NFULL);
    const float2* yr = (const float2*)(targ + (size_t)row * (size_t)NFULL);

    if (tid < 100) hist[tid] = 0u;

    // ---- one-time twiddle tables ----
    #pragma unroll
    for (int it = 0; it < 4; it++){
        int t = tid + it * 512;
        float s, c; sincospif(-(float)t * (1.0f/4096.0f), &s, &c);
        Wt[t] = make_float2(c, s);
    }
    if (tid < 16){ float s, c; sincospif(-(float)tid * (1.0f/128.0f),  &s, &c); w4t[tid] = make_float2(c, s); }
    if (tid < 256){ float s, c; sincospif(-(float)tid * (1.0f/2048.0f), &s, &c); w8t[tid] = make_float2(c, s); }

    // ---- load (AoS natural order) + Pearson moments + min/max ----
    float sx = 0.f, sy = 0.f, sxy = 0.f, sx2 = 0.f, sy2 = 0.f;
    float xmn = INFINITY, xmx = -INFINITY, ymn = INFINITY, ymx = -INFINITY;
    #pragma unroll 4
    for (int it = 0; it < 16; it++){
        int n = tid + it * THREADS;
        float2 a = xr[n], b = yr[n];
        sx  += a.x + a.y;          sy  += b.x + b.y;
        sxy += a.x*b.x + a.y*b.y;
        sx2 += a.x*a.x + a.y*a.y;  sy2 += b.x*b.x + b.y*b.y;
        xmn = fminf(xmn, fminf(a.x, a.y)); xmx = fmaxf(xmx, fmaxf(a.x, a.y));
        ymn = fminf(ymn, fminf(b.x, b.y)); ymx = fmaxf(ymx, fmaxf(b.x, b.y));
        Ap[n] = a; Bp[n] = b;
    }
    sx  = warp_sum(sx);  sy  = warp_sum(sy); sxy = warp_sum(sxy);
    sx2 = warp_sum(sx2); sy2 = warp_sum(sy2);
    #pragma unroll
    for (int o = 16; o; o >>= 1){
        xmn = fminf(xmn, __shfl_down_sync(0xffffffffu, xmn, o));
        xmx = fmaxf(xmx, __shfl_down_sync(0xffffffffu, xmx, o));
        ymn = fminf(ymn, __shfl_down_sync(0xffffffffu, ymn, o));
        ymx = fmaxf(ymx, __shfl_down_sync(0xffffffffu, ymx, o));
    }
    if (lane == 0){
        s_red[warp][0]=sx;  s_red[warp][1]=sy;  s_red[warp][2]=sxy;
        s_red[warp][3]=sx2; s_red[warp][4]=sy2;
        s_red[warp][5]=xmn; s_red[warp][6]=xmx; s_red[warp][7]=ymn; s_red[warp][8]=ymx;
    }
    __syncthreads();
    if (tid == 0){
        double Sx=0,Sy=0,Sxy=0,Sx2=0,Sy2=0;
        float a = s_red[0][5], b = s_red[0][6], c = s_red[0][7], d = s_red[0][8];
        for (int w = 0; w < NWARP; w++){
            Sx+=s_red[w][0]; Sy+=s_red[w][1]; Sxy+=s_red[w][2];
            Sx2+=s_red[w][3]; Sy2+=s_red[w][4];
            a = fminf(a, s_red[w][5]); b = fmaxf(b, s_red[w][6]);
            c = fminf(c, s_red[w][7]); d = fmaxf(d, s_red[w][8]);
        }
        const double N = (double)NFULL;
        r_pear = 1.0 - (N*Sxy - Sx*Sy) / sqrt((N*Sx2 - Sx*Sx) * (N*Sy2 - Sy*Sy));
        s_mm[0]=a; s_mm[1]=b; s_mm[2]=c; s_mm[3]=d;
    }
    __syncthreads();

    // ---- merged forward pass 1 (L=1) for BOTH arrays + MI histogram ----
    {
        const float xmin = s_mm[0], ymin = s_mm[2];
        const float bwx = __fdiv_rn(s_mm[1] - s_mm[0], 10.0f);
        const float bwy = __fdiv_rn(s_mm[3] - s_mm[2], 10.0f);
        int j = tid;
        float2 xa[16], xb[16];
        #pragma unroll
        for (int c = 0; c < 16; c++){
            int n = j + 512*c;
            float2 a = Ap[n];
            float2 b = Bp[n];
            xa[c] = a; xb[c] = b;
            int ix0 = min(max((int)__fdiv_rn(a.x - xmin, bwx), 0), 9);
            int iy0 = min(max((int)__fdiv_rn(b.x - ymin, bwy), 0), 9);
            int ix1 = min(max((int)__fdiv_rn(a.y - xmin, bwx), 0), 9);
            int iy1 = min(max((int)__fdiv_rn(b.y - ymin, bwy), 0), 9);
            atomicAdd(&hist[ix0 * 10 + iy0], 1u);
            atomicAdd(&hist[ix1 * 10 + iy1], 1u);
        }
        fft16<0>(xa);
        fft16<0>(xb);
        __syncthreads();            // reads complete -> in-place writes safe
        #pragma unroll
        for (int c = 0; c < 16; c++){
            int a = swz1(16*j + c);
            Ap[a] = xa[c]; Bp[a] = xb[c];
        }
    }
    __syncthreads();

    // ---- MI final math on warp 0 (hist stable; other warps proceed) ----
    if (warp == 0){
        const float eps = 1e-8f;
        const float invD = 1.0f / 8388608.0f;   // 1/(B*S), faithful to reference
        if (lane < 10){
            float hx = 0.f, hy = 0.f;
            for (int j = 0; j < 10; j++){
                hx += (float)hist[lane*10 + j];
                hy += (float)hist[j*10 + lane];
            }
            s_hx[lane] = hx; s_hy[lane] = hy;
        }
        __syncwarp();
        float mi = 0.f;
        for (int b = lane; b < 100; b += 32){
            float px  = s_hx[b/10] * invD;
            float py  = s_hy[b%10] * invD;
            float pxy = (float)hist[b] * invD;
            mi += pxy * logf(__fdiv_rn(pxy + eps, px * py + eps));
        }
        mi = warp_sum(mi);
        float he = 0.f;
        if (lane < 10){
            float px = s_hx[lane] * invD, py = s_hy[lane] * invD;
            he = -px * logf(px + eps) - py * logf(py + eps);
        }
        he = warp_sum(he);
        if (lane == 0) r_nmi = (double)(mi / (0.5f * he));
    }

    mpassR16<4,1>(Ap, Bp, w4t); __syncthreads();
    mpassR16<8,0>(Ap, Bp, w8t); __syncthreads();
    mpass2(Ap, Bp, Wt);         __syncthreads();   // pred spectrum in A, targ in B

    // ---- spectra: power-spectrum sums + hann-windowed phase correlation -> C ----
    float accd = 0.f, acct = 0.f;
    float2 lastX0p, lastX0t, lastXpp, lastXpt;
    for (int it = 0; it < 16; it++){
        int k = tid + it * 512;               // 0..8191
        float2 w0 = twget16k<0>(Wt, k);
        float2 X0p = spec_at(Ap, k, w0);
        float2 X0t = spec_at(Bp, k, w0);
        float2 Xmp, Xmt, Xpp, Xpt;
        Xmp.x = __shfl_up_sync(0xffffffffu, X0p.x, 1);
        Xmp.y = __shfl_up_sync(0xffffffffu, X0p.y, 1);
        Xmt.x = __shfl_up_sync(0xffffffffu, X0t.x, 1);
        Xmt.y = __shfl_up_sync(0xffffffffu, X0t.y, 1);
        Xpp.x = __shfl_down_sync(0xffffffffu, X0p.x, 1);
        Xpp.y = __shfl_down_sync(0xffffffffu, X0p.y, 1);
        Xpt.x = __shfl_down_sync(0xffffffffu, X0t.x, 1);
        Xpt.y = __shfl_down_sync(0xffffffffu, X0t.y, 1);
        if (lane == 0){
            if (k == 0){
                float2 w1 = twget16k<0>(Wt, 1);
                Xmp = cconj(spec_at(Ap, 1, w1));   // X[-1] = conj(X[1])
                Xmt = cconj(spec_at(Bp, 1, w1));
            } else {
                float2 wm = twget16k<0>(Wt, k-1);
                Xmp = spec_at(Ap, k-1, wm);
                Xmt = spec_at(Bp, k-1, wm);
            }
        }
        if (lane == 31){
            float2 wp = twget16k<0>(Wt, k+1);
            Xpp = spec_at(Ap, k+1, wp);
            Xpt = spec_at(Bp, k+1, wp);
        }
        float pp = X0p.x*X0p.x + X0p.y*X0p.y;
        float pt = X0t.x*X0t.x + X0t.y*X0t.y;
        accd += fabsf(pp - pt);
        acct += pt;
        float2 xf = csub(cadd(X0p, X0p), cadd(Xmp, Xpp));
        float2 tf = csub(cadd(X0t, X0t), cadd(Xmt, Xpt));
        float2 c = cmul(xf, cconj(tf));
        float inv = rsqrtf(c.x*c.x + c.y*c.y);
        Cp[k] = make_float2(c.x * inv, c.y * inv);
        lastX0p = X0p; lastX0t = X0t; lastXpp = Xpp; lastXpt = Xpt;
    }
    if (tid == THREADS - 1){
        // bin 8192: X0' = X[8192] (= lastXpp), Xm' = X[8191], Xp' = conj(X[8191])
        float2 X0p = lastXpp, X0t = lastXpt;
        float2 Xmp = lastX0p, Xmt = lastX0t;
        float2 Xpp = cconj(Xmp), Xpt = cconj(Xmt);
        float pp = X0p.x*X0p.x + X0p.y*X0p.y;
        float pt = X0t.x*X0t.x + X0t.y*X0t.y;
        accd += fabsf(pp - pt);
        acct += pt;
        float2 xf = csub(cadd(X0p, X0p), cadd(Xmp, Xpp));
        float2 tf = csub(cadd(X0t, X0t), cadd(Xmt, Xpt));
        float2 c = cmul(xf, cconj(tf));
        float inv = rsqrtf(c.x*c.x + c.y*c.y);
        s_c8192 = make_float2(c.x * inv, c.y * inv);
    }
    accd = warp_sum(accd); acct = warp_sum(acct);
    if (lane == 0){ s_red[warp][0] = accd; s_red[warp][1] = acct; }
    __syncthreads();
    if (tid == 0){
        double d = 0.0, t2 = 0.0;
        for (int w = 0; w < NWARP; w++){ d += s_red[w][0]; t2 += s_red[w][1]; }
        r_absd = d; r_tp = t2;
    }

    // ---- inverse pass 1 with spectrum-pack folded in: C -> A (swz1 writes) ----
    {
        int j = tid;
        float2 x[16];
        #pragma unroll
        for (int c = 0; c < 16; c++){
            int n = j + 512*c;
            float2 Bn = Cp[n];
            float2 Bm = (n == 0) ? s_c8192 : cconj(Cp[8192 - n]);  // conj(C[8192-n])
            float2 E = cadd(Bn, Bm);
            float2 D = csub(Bn, Bm);
            float2 wn = twget16k<1>(Wt, n);          // e^{+i pi n/8192}
            float2 O  = cmul(wn, D);
            x[c] = make_float2(E.x - O.y, E.y + O.x);  // E + i*O
        }
        fft16<1>(x);
        #pragma unroll
        for (int c = 0; c < 16; c++) Ap[swz1(16*j + c)] = x[c];
    }
    __syncthreads();

    passR16<4,1,1>(Ap, Cp, w4t); __syncthreads();
    passR16<8,1,0>(Cp, Ap, w8t); __syncthreads();   // inverse penultimate in A

    // ---- argmax with final radix-2 pass folded in (first-occurrence tie break) ----
    float best = -INFINITY; int bi = 0x7fffffff;
    #pragma unroll 2
    for (int it = 0; it < 8; it++){
        int jj = tid + it * 512;              // 0..4095
        float2 u = Ap[jj];
        float2 v = Ap[jj + 4096];
        float2 wv = cmul(v, twget<1>(Wt, jj));
        float y0r = u.x + wv.x, y0i = u.y + wv.y;   // Z[jj]      -> times 2jj, 2jj+1
        float y1r = u.x - wv.x, y1i = u.y - wv.y;   // Z[jj+4096] -> times 2jj+8192, +8193
        int e0 = 2*jj, o0 = 2*jj + 1, e1 = 2*jj + 8192, o1 = 2*jj + 8193;
        if (y0r > best || (y0r == best && e0 < bi)){ best = y0r; bi = e0; }
        if (y0i > best || (y0i == best && o0 < bi)){ best = y0i; bi = o0; }
        if (y1r > best || (y1r == best && e1 < bi)){ best = y1r; bi = e1; }
        if (y1i > best || (y1i == best && o1 < bi)){ best = y1i; bi = o1; }
    }
    #pragma unroll
    for (int off = 16; off; off >>= 1){
        float ov = __shfl_down_sync(0xffffffffu, best, off);
        int   oi = __shfl_down_sync(0xffffffffu, bi,   off);
        if (ov > best || (ov == best && oi < bi)){ best = ov; bi = oi; }
    }
    if (lane == 0){ s_red[warp][0] = best; s_idx[warp] = bi; }
    __syncthreads();
    if (tid == 0){
        best = s_red[0][0]; bi = s_idx[0];
        for (int w = 1; w < NWARP; w++){
            float v = s_red[w][0]; int ix = s_idx[w];
            if (v > best || (v == best && ix < bi)){ best = v; bi = ix; }
        }
        r_cos = (double)cosf(2.0f * (float)PI_D * (float)bi / 16384.0f);

        // publish this row's results (release), then arrive
        g_row[row].pear = r_pear;
        g_row[row].cosv = r_cos;
        g_row[row].absd = r_absd;
        g_row[row].tp   = r_tp;
        g_row[row].nmi  = r_nmi;
        __threadfence();
        unsigned prev = atomicAdd(&g_done, 1u);
        s_last = ((prev % ROWS) == ROWS - 1) ? 1u : 0u;
        if (s_last) __threadfence();   // acquire: order g_row reads after counter observation
    }
    __syncthreads();

    // ---- last CTA reduces all rows and writes the scalar loss ----
    if (s_last){
        double pe = 0.0, co = 0.0, ad = 0.0, tp = 0.0, nm = 0.0;
        for (int r = tid; r < ROWS; r += THREADS){
            const double* p = (const double*)&g_row[r];
            pe += __ldcg(p + 0);
            co += __ldcg(p + 1);
            ad += __ldcg(p + 2);
            tp += __ldcg(p + 3);
            nm += __ldcg(p + 4);
        }
        pe = warp_sum_d(pe); co = warp_sum_d(co); ad = warp_sum_d(ad);
        tp = warp_sum_d(tp); nm = warp_sum_d(nm);
        if (lane == 0){
            s_fin[warp][0]=pe; s_fin[warp][1]=co; s_fin[warp][2]=ad;
            s_fin[warp][3]=tp; s_fin[warp][4]=nm;
        }
        __syncthreads();
        if (tid == 0){
            double Pe=0, Co=0, Ad=0, Tp=0, Nm=0;
            for (int w = 0; w < NWARP; w++){
                Pe+=s_fin[w][0]; Co+=s_fin[w][1]; Ad+=s_fin[w][2];
                Tp+=s_fin[w][3]; Nm+=s_fin[w][4];
            }
            int ep = *pep;
            double loss = Pe / (double)ROWS;
            if (ep >= 400){
                loss += 1.0 - Co / (double)ROWS;   // phase correlation
                loss += Ad / Tp;                   // power spectrum
            }
            if (ep >= 700){
                loss += 1.0 - Nm / (double)ROWS;   // mutual information
            }
            out[0] = (float)loss;
        }
    }
}

// ---------------- launch ----------------
extern "C" void kernel_launch(void* const* d_in, const int* in_sizes, int n_in,
                              void* d_out, int out_size){
    const float* pred = (const float*)d_in[0];
    const float* targ = (const float*)d_in[1];
    const int*   pi   = (const int*)d_in[2];
    const int*   pep  = (const int*)d_in[3];
    float* out = (float*)d_out;

    // 3 planes of 8192 float2 + (2048+16+256) float2 twiddles = 215168 bytes
    const size_t smem_bytes = (size_t)(24576 + 2048 + 16 + 256) * sizeof(float2);
    cudaFuncSetAttribute(row_kernel, cudaFuncAttributeMaxDynamicSharedMemorySize,
                         (int)smem_bytes);

    row_kernel<<<ROWS, THREADS, smem_bytes>>>(pred, targ, pi, pep, out);
}